// round 1
// baseline (speedup 1.0000x reference)
#include <cuda_runtime.h>
#include <cuda_bf16.h>
#include <math.h>

// Problem dims (fixed)
#define TT 512
#define BB 512
#define DD 512
#define HH 512
#define BH (BB * HH)  // 262144

// Scratch: xp = X @ W_ih^T + bias for all timesteps (512 MB), h ping-pong buffers.
__device__ float g_xp[(size_t)TT * BB * HH];
__device__ float g_h[2][BH];

// ---------------------------------------------------------------------------
// Phase 1: xp[M=T*B, N=H] = X[M, D] @ W_ih[N, D]^T + (b_ih + b_hh)
// 128x128 tile, BK=8, 256 threads, 8x8 microtile. Writes g_xp.
// ---------------------------------------------------------------------------
__global__ __launch_bounds__(256) void xp_gemm_kernel(
    const float* __restrict__ X,
    const float* __restrict__ Wih,
    const float* __restrict__ bih,
    const float* __restrict__ bhh)
{
    __shared__ float As[8][128];
    __shared__ float Bs[8][128];

    const int tid = threadIdx.x;
    const size_t bm = (size_t)blockIdx.y * 128;
    const int bn = blockIdx.x * 128;

    const int lrow = tid >> 1;        // 0..127
    const int lk   = (tid & 1) * 4;   // 0 or 4
    const int tx   = tid & 15;        // N dir
    const int ty   = tid >> 4;        // M dir

    float acc[8][8];
#pragma unroll
    for (int i = 0; i < 8; ++i)
#pragma unroll
        for (int j = 0; j < 8; ++j) acc[i][j] = 0.0f;

    const float* Xp = X + (bm + (size_t)lrow) * DD + lk;
    const float* Wp = Wih + ((size_t)(bn + lrow)) * DD + lk;

    for (int k0 = 0; k0 < DD; k0 += 8) {
        float4 av = *(const float4*)(Xp + k0);
        float4 wv = *(const float4*)(Wp + k0);
        __syncthreads();
        As[lk + 0][lrow] = av.x; As[lk + 1][lrow] = av.y;
        As[lk + 2][lrow] = av.z; As[lk + 3][lrow] = av.w;
        Bs[lk + 0][lrow] = wv.x; Bs[lk + 1][lrow] = wv.y;
        Bs[lk + 2][lrow] = wv.z; Bs[lk + 3][lrow] = wv.w;
        __syncthreads();
#pragma unroll
        for (int k = 0; k < 8; ++k) {
            float a0[8], b0[8];
            *(float4*)&a0[0] = *(const float4*)&As[k][ty * 8];
            *(float4*)&a0[4] = *(const float4*)&As[k][ty * 8 + 4];
            *(float4*)&b0[0] = *(const float4*)&Bs[k][tx * 8];
            *(float4*)&b0[4] = *(const float4*)&Bs[k][tx * 8 + 4];
#pragma unroll
            for (int i = 0; i < 8; ++i)
#pragma unroll
                for (int j = 0; j < 8; ++j)
                    acc[i][j] += a0[i] * b0[j];
        }
    }

    float bias[8];
#pragma unroll
    for (int j = 0; j < 8; ++j) {
        int n = bn + tx * 8 + j;
        bias[j] = bih[n] + bhh[n];
    }
#pragma unroll
    for (int i = 0; i < 8; ++i) {
        size_t row = bm + (size_t)(ty * 8 + i);
        float* crow = g_xp + row * HH + bn + tx * 8;
#pragma unroll
        for (int j = 0; j < 8; ++j)
            crow[j] = acc[i][j] + bias[j];
    }
}

// ---------------------------------------------------------------------------
// Step 0: h1 = tanh(xp_0)   (h0 == 0, so the GEMM term vanishes)
// ---------------------------------------------------------------------------
__global__ __launch_bounds__(256) void step0_kernel(
    const float* __restrict__ xp0, float* __restrict__ hout)
{
    int i = blockIdx.x * blockDim.x + threadIdx.x;  // float4 index, 65536 total
    float4 v = ((const float4*)xp0)[i];
    v.x = tanhf(v.x); v.y = tanhf(v.y);
    v.z = tanhf(v.z); v.w = tanhf(v.w);
    ((float4*)hout)[i] = v;
}

// ---------------------------------------------------------------------------
// Recurrence step: hout = tanh(xp_t + hin @ W_hh^T)
// 64x64 tile, BK=16, 256 threads, 4x4 microtile. Grid 8x8 = 64 CTAs.
// ---------------------------------------------------------------------------
__global__ __launch_bounds__(256) void rnn_step_kernel(
    const float* __restrict__ hin,
    const float* __restrict__ Whh,
    const float* __restrict__ xp_t,
    float* __restrict__ hout)
{
    __shared__ float As[16][64];
    __shared__ float Bs[16][64];

    const int tid = threadIdx.x;
    const int bm = blockIdx.y * 64;
    const int bn = blockIdx.x * 64;

    const int lrow = tid >> 2;        // 0..63
    const int lk   = (tid & 3) * 4;   // 0,4,8,12
    const int tx   = tid & 15;
    const int ty   = tid >> 4;

    float acc[4][4];
#pragma unroll
    for (int i = 0; i < 4; ++i)
#pragma unroll
        for (int j = 0; j < 4; ++j) acc[i][j] = 0.0f;

    const float* Ap = hin + (size_t)(bm + lrow) * HH + lk;
    const float* Wp = Whh + (size_t)(bn + lrow) * HH + lk;

    for (int k0 = 0; k0 < HH; k0 += 16) {
        float4 av = *(const float4*)(Ap + k0);
        float4 wv = *(const float4*)(Wp + k0);
        __syncthreads();
        As[lk + 0][lrow] = av.x; As[lk + 1][lrow] = av.y;
        As[lk + 2][lrow] = av.z; As[lk + 3][lrow] = av.w;
        Bs[lk + 0][lrow] = wv.x; Bs[lk + 1][lrow] = wv.y;
        Bs[lk + 2][lrow] = wv.z; Bs[lk + 3][lrow] = wv.w;
        __syncthreads();
#pragma unroll
        for (int k = 0; k < 16; ++k) {
            float4 a = *(const float4*)&As[k][ty * 4];
            float4 b = *(const float4*)&Bs[k][tx * 4];
            acc[0][0] += a.x * b.x; acc[0][1] += a.x * b.y;
            acc[0][2] += a.x * b.z; acc[0][3] += a.x * b.w;
            acc[1][0] += a.y * b.x; acc[1][1] += a.y * b.y;
            acc[1][2] += a.y * b.z; acc[1][3] += a.y * b.w;
            acc[2][0] += a.z * b.x; acc[2][1] += a.z * b.y;
            acc[2][2] += a.z * b.z; acc[2][3] += a.z * b.w;
            acc[3][0] += a.w * b.x; acc[3][1] += a.w * b.y;
            acc[3][2] += a.w * b.z; acc[3][3] += a.w * b.w;
        }
    }

#pragma unroll
    for (int i = 0; i < 4; ++i) {
        int row = bm + ty * 4 + i;
        const float* xrow = xp_t + (size_t)row * HH + bn + tx * 4;
        float* orow = hout + (size_t)row * HH + bn + tx * 4;
#pragma unroll
        for (int j = 0; j < 4; ++j)
            orow[j] = tanhf(acc[i][j] + xrow[j]);
    }
}

// ---------------------------------------------------------------------------
// Launcher
// ---------------------------------------------------------------------------
extern "C" void kernel_launch(void* const* d_in, const int* in_sizes, int n_in,
                              void* d_out, int out_size)
{
    const float* X   = (const float*)d_in[0];  // [T, B, D]
    const float* Wih = (const float*)d_in[1];  // [H, D]
    const float* Whh = (const float*)d_in[2];  // [H, H]
    const float* bih = (const float*)d_in[3];  // [H]
    const float* bhh = (const float*)d_in[4];  // [H]
    float* out = (float*)d_out;                // [B, H]

    float* xp = nullptr;
    float* h  = nullptr;
    cudaGetSymbolAddress((void**)&xp, g_xp);
    cudaGetSymbolAddress((void**)&h,  g_h);

    // Phase 1: xp for all timesteps. grid = (N/128, M/128) = (4, 2048)
    dim3 g1(4, 2048);
    xp_gemm_kernel<<<g1, 256>>>(X, Wih, bih, bhh);

    // Step 0: h = tanh(xp_0)
    step0_kernel<<<BH / 4 / 256, 256>>>(xp, h);

    // Steps 1..511 (last step writes d_out directly)
    dim3 gs(8, 8);
    for (int t = 1; t < TT; ++t) {
        const float* hin = h + (size_t)((t - 1) & 1) * BH;
        float* hout = (t == TT - 1) ? out : (h + (size_t)(t & 1) * BH);
        rnn_step_kernel<<<gs, 256>>>(hin, Whh, xp + (size_t)t * BH, hout);
    }
}

// round 3
// speedup vs baseline: 3.4464x; 3.4464x over previous
#include <cuda_runtime.h>
#include <cuda_bf16.h>
#include <math.h>
#include <stdint.h>

// Problem dims (fixed)
#define TT 512
#define BB 512
#define DD 512
#define HH 512
#define BH (BB * HH)  // 262144

// -------------------- device scratch (no allocations allowed) --------------
__device__ float          g_xp[(size_t)TT * BH];            // 512 MB
__device__ __nv_bfloat16  g_xhi[(size_t)TT * BB * DD];      // 256 MB
__device__ __nv_bfloat16  g_xlo[(size_t)TT * BB * DD];      // 256 MB
__device__ __nv_bfloat16  g_wih_h[HH * DD], g_wih_l[HH * DD];
__device__ __nv_bfloat16  g_whh_h[HH * HH], g_whh_l[HH * HH];
__device__ __nv_bfloat16  g_hhi[2][BH], g_hlo[2][BH];

// -------------------- PTX helpers (sm_80-level only; no 'a' features) ------
__device__ __forceinline__ uint32_t smem_u32(const void* p) {
    uint32_t a;
    asm("{ .reg .u64 t; cvta.to.shared.u64 t, %1; cvt.u32.u64 %0, t; }" : "=r"(a) : "l"(p));
    return a;
}
__device__ __forceinline__ void cp16(uint32_t s, const void* g) {
    asm volatile("cp.async.cg.shared.global [%0], [%1], 16;" :: "r"(s), "l"(g));
}
#define CP_COMMIT() asm volatile("cp.async.commit_group;" ::: "memory")
#define CP_WAIT(n)  asm volatile("cp.async.wait_group %0;" :: "n"(n) : "memory")

__device__ __forceinline__ void ldsm4(uint32_t* r, uint32_t addr) {
    asm volatile("ldmatrix.sync.aligned.m8n8.x4.shared.b16 {%0,%1,%2,%3}, [%4];"
                 : "=r"(r[0]), "=r"(r[1]), "=r"(r[2]), "=r"(r[3]) : "r"(addr));
}
__device__ __forceinline__ void mma16816(float* d, const uint32_t* a, uint32_t b0, uint32_t b1) {
    asm volatile("mma.sync.aligned.m16n8k16.row.col.f32.bf16.bf16.f32 "
                 "{%0,%1,%2,%3}, {%4,%5,%6,%7}, {%8,%9}, {%0,%1,%2,%3};"
                 : "+f"(d[0]), "+f"(d[1]), "+f"(d[2]), "+f"(d[3])
                 : "r"(a[0]), "r"(a[1]), "r"(a[2]), "r"(a[3]), "r"(b0), "r"(b1));
}

// -------------------- split helpers ----------------------------------------
__device__ __forceinline__ void split1(float x, __nv_bfloat16& h, __nv_bfloat16& l) {
    h = __float2bfloat16_rn(x);
    l = __float2bfloat16_rn(x - __bfloat162float(h));
}

__global__ __launch_bounds__(256) void split_kernel(const float* __restrict__ src,
                                                    __nv_bfloat16* __restrict__ hi,
                                                    __nv_bfloat16* __restrict__ lo, int n4) {
    for (int i = blockIdx.x * blockDim.x + threadIdx.x; i < n4; i += gridDim.x * blockDim.x) {
        float4 v = ((const float4*)src)[i];
        __nv_bfloat16 h0, h1, h2, h3, l0, l1, l2, l3;
        split1(v.x, h0, l0); split1(v.y, h1, l1);
        split1(v.z, h2, l2); split1(v.w, h3, l3);
        __nv_bfloat162* ph = (__nv_bfloat162*)hi;
        __nv_bfloat162* pl = (__nv_bfloat162*)lo;
        ph[i * 2] = __nv_bfloat162(h0, h1); ph[i * 2 + 1] = __nv_bfloat162(h2, h3);
        pl[i * 2] = __nv_bfloat162(l0, l1); pl[i * 2 + 1] = __nv_bfloat162(l2, l3);
    }
}

// h1 = tanh(xp_0)  (h0 == 0), emitted as hi/lo bf16
__global__ __launch_bounds__(256) void step0_kernel(const float* __restrict__ xp0,
                                                    __nv_bfloat16* __restrict__ hhi,
                                                    __nv_bfloat16* __restrict__ hlo) {
    for (int i = blockIdx.x * blockDim.x + threadIdx.x; i < BH / 4; i += gridDim.x * blockDim.x) {
        float4 v = ((const float4*)xp0)[i];
        v.x = tanhf(v.x); v.y = tanhf(v.y); v.z = tanhf(v.z); v.w = tanhf(v.w);
        __nv_bfloat16 h0, h1, h2, h3, l0, l1, l2, l3;
        split1(v.x, h0, l0); split1(v.y, h1, l1);
        split1(v.z, h2, l2); split1(v.w, h3, l3);
        __nv_bfloat162* ph = (__nv_bfloat162*)hhi;
        __nv_bfloat162* pl = (__nv_bfloat162*)hlo;
        ph[i * 2] = __nv_bfloat162(h0, h1); ph[i * 2 + 1] = __nv_bfloat162(h2, h3);
        pl[i * 2] = __nv_bfloat162(l0, l1); pl[i * 2 + 1] = __nv_bfloat162(l2, l3);
    }
}

// -------------------- async tile loader ------------------------------------
// Loads ROWS x 64 bf16 (128B per row) into smem with SW128-style swizzle.
template <int ROWS, int THREADS>
__device__ __forceinline__ void load_tile_async(const __nv_bfloat16* __restrict__ g,
                                                size_t row0, int kbase,
                                                uint32_t sdst, int tid) {
    constexpr int TOT = ROWS * 8;  // 16B granules
#pragma unroll
    for (int i = 0; i < TOT / THREADS; ++i) {
        int v = i * THREADS + tid;
        int row = v >> 3, g16 = v & 7;
        uint32_t off = (uint32_t)(row * 128 + ((g16 * 16) ^ ((row & 7) * 16)));
        cp16(sdst + off, g + (row0 + (size_t)row) * HH + kbase + g16 * 8);
    }
}

// -------------------- split-bf16 GEMM via mma.sync -------------------------
// C[M,N] = (Ahi+Alo)[M,K] @ (Bhi+Blo)[N,K]^T  (lo*lo dropped), K = 512, BK = 64.
// IS_STEP: C = tanh(C + xp_t) -> out_hi/out_lo (and optional out_f)
// else:    C = C + bih + bhh  -> out_f
template <int BM, int BN, int WM, int WN, bool IS_STEP>
__global__ void __launch_bounds__((BM / WM) * (BN / WN) * 32, 1)
gemm_split_kernel(const __nv_bfloat16* __restrict__ Ahi, const __nv_bfloat16* __restrict__ Alo,
                  const __nv_bfloat16* __restrict__ Bhi, const __nv_bfloat16* __restrict__ Blo,
                  const float* __restrict__ xp_t,
                  const float* __restrict__ bih, const float* __restrict__ bhh,
                  float* __restrict__ out_f,
                  __nv_bfloat16* __restrict__ out_hi, __nv_bfloat16* __restrict__ out_lo)
{
    constexpr int THREADS = (BM / WM) * (BN / WN) * 32;
    constexpr int SA = BM * 128;      // bytes per A tile (one split)
    constexpr int SB = BN * 128;
    constexpr int STAGE = 2 * SA + 2 * SB;
    constexpr int NCHUNK = HH / 64;   // 8

    extern __shared__ char smem[];
    const uint32_t sbase = smem_u32(smem);
    const int tid = threadIdx.x;
    const int wid = tid >> 5, lane = tid & 31;
    const size_t bm = (size_t)blockIdx.y * BM;
    const int bn = blockIdx.x * BN;
    const int wm = (wid % (BM / WM)) * WM;
    const int wn = (wid / (BM / WM)) * WN;

    float acc[WM / 16][WN / 8][4];
#pragma unroll
    for (int mi = 0; mi < WM / 16; ++mi)
#pragma unroll
        for (int ni = 0; ni < WN / 8; ++ni)
#pragma unroll
            for (int q = 0; q < 4; ++q) acc[mi][ni][q] = 0.0f;

    // ldmatrix lane geometry (A and B both K-major, non-transposed x4)
    const int sub = lane >> 3, li = lane & 7;
    const int arow = (sub & 1) * 8 + li;   // + akb selects k-halves
    const int akb  = (sub >> 1) * 16;
    const int brow = (sub >> 1) * 8 + li;
    const int bkb  = (sub & 1) * 16;
    const uint32_t swx = (uint32_t)(li * 16);  // (row&7)*16 for both (wm, wn mult of 16)

    auto issue_loads = [&](int c, int s) {
        const uint32_t st = sbase + (uint32_t)(s * STAGE);
        const int kb = c * 64;
        load_tile_async<BM, THREADS>(Ahi, bm, kb, st, tid);
        load_tile_async<BM, THREADS>(Alo, bm, kb, st + SA, tid);
        load_tile_async<BN, THREADS>(Bhi, (size_t)bn, kb, st + 2 * SA, tid);
        load_tile_async<BN, THREADS>(Blo, (size_t)bn, kb, st + 2 * SA + SB, tid);
        CP_COMMIT();
    };

    issue_loads(0, 0);

    for (int c = 0; c < NCHUNK; ++c) {
        if (c + 1 < NCHUNK) {
            issue_loads(c + 1, (c + 1) & 1);
            CP_WAIT(1);
        } else {
            CP_WAIT(0);
        }
        __syncthreads();

        const uint32_t st = sbase + (uint32_t)((c & 1) * STAGE);
        const uint32_t aHi = st + (uint32_t)((wm + arow) * 128);
        const uint32_t aLo = aHi + SA;
        const uint32_t bHi = st + 2 * SA + (uint32_t)((wn + brow) * 128);
        const uint32_t bLo = bHi + SB;

#pragma unroll
        for (int kk = 0; kk < 4; ++kk) {
            const uint32_t ka = (uint32_t)(kk * 32 + akb) ^ swx;
            const uint32_t kb2 = (uint32_t)(kk * 32 + bkb) ^ swx;
            uint32_t ah[WM / 16][4], al[WM / 16][4], bh[WN / 16][4], bl[WN / 16][4];
#pragma unroll
            for (int mi = 0; mi < WM / 16; ++mi) {
                ldsm4(ah[mi], aHi + mi * 2048 + ka);
                ldsm4(al[mi], aLo + mi * 2048 + ka);
            }
#pragma unroll
            for (int nj = 0; nj < WN / 16; ++nj) {
                ldsm4(bh[nj], bHi + nj * 2048 + kb2);
                ldsm4(bl[nj], bLo + nj * 2048 + kb2);
            }
            // hi*hi
#pragma unroll
            for (int mi = 0; mi < WM / 16; ++mi)
#pragma unroll
                for (int ni = 0; ni < WN / 8; ++ni)
                    mma16816(acc[mi][ni], ah[mi],
                             bh[ni >> 1][2 * (ni & 1)], bh[ni >> 1][2 * (ni & 1) + 1]);
            // hi*lo
#pragma unroll
            for (int mi = 0; mi < WM / 16; ++mi)
#pragma unroll
                for (int ni = 0; ni < WN / 8; ++ni)
                    mma16816(acc[mi][ni], ah[mi],
                             bl[ni >> 1][2 * (ni & 1)], bl[ni >> 1][2 * (ni & 1) + 1]);
            // lo*hi
#pragma unroll
            for (int mi = 0; mi < WM / 16; ++mi)
#pragma unroll
                for (int ni = 0; ni < WN / 8; ++ni)
                    mma16816(acc[mi][ni], al[mi],
                             bh[ni >> 1][2 * (ni & 1)], bh[ni >> 1][2 * (ni & 1) + 1]);
        }
        __syncthreads();
    }

    // Epilogue. c0,c1 -> (row, col..col+1); c2,c3 -> (row+8, col..col+1)
    const int g = lane >> 2, tg = lane & 3;
#pragma unroll
    for (int mi = 0; mi < WM / 16; ++mi) {
#pragma unroll
        for (int ni = 0; ni < WN / 8; ++ni) {
            const size_t r0 = bm + (size_t)(wm + mi * 16 + g);
            const size_t r1 = r0 + 8;
            const int c0 = bn + wn + ni * 8 + 2 * tg;
            if (IS_STEP) {
                float2 x0 = *(const float2*)(xp_t + r0 * HH + c0);
                float2 x1 = *(const float2*)(xp_t + r1 * HH + c0);
                float v0 = tanhf(acc[mi][ni][0] + x0.x);
                float v1 = tanhf(acc[mi][ni][1] + x0.y);
                float v2 = tanhf(acc[mi][ni][2] + x1.x);
                float v3 = tanhf(acc[mi][ni][3] + x1.y);
                __nv_bfloat16 h0, l0, h1, l1, h2, l2, h3, l3;
                split1(v0, h0, l0); split1(v1, h1, l1);
                split1(v2, h2, l2); split1(v3, h3, l3);
                *(__nv_bfloat162*)(out_hi + r0 * HH + c0) = __nv_bfloat162(h0, h1);
                *(__nv_bfloat162*)(out_lo + r0 * HH + c0) = __nv_bfloat162(l0, l1);
                *(__nv_bfloat162*)(out_hi + r1 * HH + c0) = __nv_bfloat162(h2, h3);
                *(__nv_bfloat162*)(out_lo + r1 * HH + c0) = __nv_bfloat162(l2, l3);
                if (out_f) {
                    *(float2*)(out_f + r0 * HH + c0) = make_float2(v0, v1);
                    *(float2*)(out_f + r1 * HH + c0) = make_float2(v2, v3);
                }
            } else {
                float b0 = bih[c0] + bhh[c0];
                float b1 = bih[c0 + 1] + bhh[c0 + 1];
                *(float2*)(out_f + r0 * HH + c0) =
                    make_float2(acc[mi][ni][0] + b0, acc[mi][ni][1] + b1);
                *(float2*)(out_f + r1 * HH + c0) =
                    make_float2(acc[mi][ni][2] + b0, acc[mi][ni][3] + b1);
            }
        }
    }
}

// -------------------- launcher ---------------------------------------------
extern "C" void kernel_launch(void* const* d_in, const int* in_sizes, int n_in,
                              void* d_out, int out_size)
{
    const float* X   = (const float*)d_in[0];  // [T, B, D]
    const float* Wih = (const float*)d_in[1];  // [H, D]
    const float* Whh = (const float*)d_in[2];  // [H, H]
    const float* bih = (const float*)d_in[3];  // [H]
    const float* bhh = (const float*)d_in[4];  // [H]
    float* out = (float*)d_out;                // [B, H]

    float* xp;
    __nv_bfloat16 *xhi, *xlo, *wih_h, *wih_l, *whh_h, *whh_l, *hhi, *hlo;
    cudaGetSymbolAddress((void**)&xp, g_xp);
    cudaGetSymbolAddress((void**)&xhi, g_xhi);
    cudaGetSymbolAddress((void**)&xlo, g_xlo);
    cudaGetSymbolAddress((void**)&wih_h, g_wih_h);
    cudaGetSymbolAddress((void**)&wih_l, g_wih_l);
    cudaGetSymbolAddress((void**)&whh_h, g_whh_h);
    cudaGetSymbolAddress((void**)&whh_l, g_whh_l);
    cudaGetSymbolAddress((void**)&hhi, g_hhi);
    cudaGetSymbolAddress((void**)&hlo, g_hlo);

    // Shared sizes: xp kernel 128KB, step kernel 64KB
    constexpr int SMEM_XP   = 2 * (2 * 128 * 128 + 2 * 128 * 128);  // 131072
    constexpr int SMEM_STEP = 2 * (2 * 64 * 128 + 2 * 64 * 128);    // 65536
    cudaFuncSetAttribute(gemm_split_kernel<128, 128, 64, 32, false>,
                         cudaFuncAttributeMaxDynamicSharedMemorySize, SMEM_XP);
    cudaFuncSetAttribute(gemm_split_kernel<64, 64, 32, 32, true>,
                         cudaFuncAttributeMaxDynamicSharedMemorySize, SMEM_STEP);

    // 1) hi/lo splits
    split_kernel<<<128, 256>>>(Wih, wih_h, wih_l, HH * DD / 4);
    split_kernel<<<128, 256>>>(Whh, whh_h, whh_l, HH * HH / 4);
    split_kernel<<<8192, 256>>>(X, xhi, xlo, (int)((size_t)TT * BB * DD / 4));

    // 2) xp = X @ Wih^T + (b_ih + b_hh) for all timesteps
    {
        dim3 g(HH / 128, (TT * BB) / 128);  // (4, 2048)
        gemm_split_kernel<128, 128, 64, 32, false><<<g, 256, SMEM_XP>>>(
            xhi, xlo, wih_h, wih_l, nullptr, bih, bhh, xp, nullptr, nullptr);
    }

    // 3) h1 = tanh(xp_0)
    step0_kernel<<<256, 256>>>(xp, hhi, hlo);

    // 4) recurrence steps 1..511
    dim3 gs(HH / 64, BB / 64);  // (8, 8)
    for (int t = 1; t < TT; ++t) {
        const __nv_bfloat16* ah = hhi + (size_t)((t - 1) & 1) * BH;
        const __nv_bfloat16* al = hlo + (size_t)((t - 1) & 1) * BH;
        __nv_bfloat16* oh = hhi + (size_t)(t & 1) * BH;
        __nv_bfloat16* ol = hlo + (size_t)(t & 1) * BH;
        float* fo = (t == TT - 1) ? out : nullptr;
        gemm_split_kernel<64, 64, 32, 32, true><<<gs, 128, SMEM_STEP>>>(
            ah, al, whh_h, whh_l, xp + (size_t)t * BH, nullptr, nullptr, fo, oh, ol);
    }
}

// round 4
// speedup vs baseline: 4.6090x; 1.3374x over previous
#include <cuda_runtime.h>
#include <cuda_bf16.h>
#include <math.h>
#include <stdint.h>

// Problem dims (fixed)
#define TT 512
#define BB 512
#define DD 512
#define HH 512
#define BH (BB * HH)  // 262144

// -------------------- device scratch (no allocations allowed) --------------
__device__ float          g_xp[(size_t)TT * BH];            // 512 MB
__device__ __nv_bfloat16  g_xhi[(size_t)TT * BB * DD];      // 256 MB
__device__ __nv_bfloat16  g_xlo[(size_t)TT * BB * DD];      // 256 MB
__device__ __nv_bfloat16  g_wih_h[HH * DD], g_wih_l[HH * DD];
__device__ __nv_bfloat16  g_whh_h[HH * HH], g_whh_l[HH * HH];
__device__ __nv_bfloat16  g_hhi[2][BH], g_hlo[2][BH];

// grid barrier state (self-restoring: count returns to 0 every barrier;
// phase is read fresh at each launch, so graph replays are safe)
__device__ unsigned g_bar_count = 0;
__device__ volatile unsigned g_bar_phase = 0;

// -------------------- PTX helpers (sm_80-level only; no 'a' features) ------
__device__ __forceinline__ uint32_t smem_u32(const void* p) {
    uint32_t a;
    asm("{ .reg .u64 t; cvta.to.shared.u64 t, %1; cvt.u32.u64 %0, t; }" : "=r"(a) : "l"(p));
    return a;
}
__device__ __forceinline__ void cp16(uint32_t s, const void* g) {
    asm volatile("cp.async.cg.shared.global [%0], [%1], 16;" :: "r"(s), "l"(g));
}
#define CP_COMMIT() asm volatile("cp.async.commit_group;" ::: "memory")
#define CP_WAIT(n)  asm volatile("cp.async.wait_group %0;" :: "n"(n) : "memory")

__device__ __forceinline__ void ldsm4(uint32_t* r, uint32_t addr) {
    asm volatile("ldmatrix.sync.aligned.m8n8.x4.shared.b16 {%0,%1,%2,%3}, [%4];"
                 : "=r"(r[0]), "=r"(r[1]), "=r"(r[2]), "=r"(r[3]) : "r"(addr));
}
__device__ __forceinline__ void mma16816(float* d, const uint32_t* a, uint32_t b0, uint32_t b1) {
    asm volatile("mma.sync.aligned.m16n8k16.row.col.f32.bf16.bf16.f32 "
                 "{%0,%1,%2,%3}, {%4,%5,%6,%7}, {%8,%9}, {%0,%1,%2,%3};"
                 : "+f"(d[0]), "+f"(d[1]), "+f"(d[2]), "+f"(d[3])
                 : "r"(a[0]), "r"(a[1]), "r"(a[2]), "r"(a[3]), "r"(b0), "r"(b1));
}

// -------------------- split helpers ----------------------------------------
__device__ __forceinline__ void split1(float x, __nv_bfloat16& h, __nv_bfloat16& l) {
    h = __float2bfloat16_rn(x);
    l = __float2bfloat16_rn(x - __bfloat162float(h));
}

__global__ __launch_bounds__(256) void split_kernel(const float* __restrict__ src,
                                                    __nv_bfloat16* __restrict__ hi,
                                                    __nv_bfloat16* __restrict__ lo, int n4) {
    for (int i = blockIdx.x * blockDim.x + threadIdx.x; i < n4; i += gridDim.x * blockDim.x) {
        float4 v = ((const float4*)src)[i];
        __nv_bfloat16 h0, h1, h2, h3, l0, l1, l2, l3;
        split1(v.x, h0, l0); split1(v.y, h1, l1);
        split1(v.z, h2, l2); split1(v.w, h3, l3);
        __nv_bfloat162* ph = (__nv_bfloat162*)hi;
        __nv_bfloat162* pl = (__nv_bfloat162*)lo;
        ph[i * 2] = __nv_bfloat162(h0, h1); ph[i * 2 + 1] = __nv_bfloat162(h2, h3);
        pl[i * 2] = __nv_bfloat162(l0, l1); pl[i * 2 + 1] = __nv_bfloat162(l2, l3);
    }
}

// -------------------- async tile loader (generic, 64-col bf16 tiles) -------
template <int ROWS, int THREADS>
__device__ __forceinline__ void load_tile_async(const __nv_bfloat16* __restrict__ g,
                                                size_t row0, int kbase,
                                                uint32_t sdst, int tid) {
    constexpr int TOT = ROWS * 8;  // 16B granules
#pragma unroll
    for (int i = 0; i < TOT / THREADS; ++i) {
        int v = i * THREADS + tid;
        int row = v >> 3, g16 = v & 7;
        uint32_t off = (uint32_t)(row * 128 + ((g16 * 16) ^ ((row & 7) * 16)));
        cp16(sdst + off, g + (row0 + (size_t)row) * HH + kbase + g16 * 8);
    }
}

// -------------------- xp GEMM (unchanged from round 3, IS_STEP=false) ------
template <int BM, int BN, int WM, int WN, bool IS_STEP>
__global__ void __launch_bounds__((BM / WM) * (BN / WN) * 32, 1)
gemm_split_kernel(const __nv_bfloat16* __restrict__ Ahi, const __nv_bfloat16* __restrict__ Alo,
                  const __nv_bfloat16* __restrict__ Bhi, const __nv_bfloat16* __restrict__ Blo,
                  const float* __restrict__ xp_t,
                  const float* __restrict__ bih, const float* __restrict__ bhh,
                  float* __restrict__ out_f,
                  __nv_bfloat16* __restrict__ out_hi, __nv_bfloat16* __restrict__ out_lo)
{
    constexpr int THREADS = (BM / WM) * (BN / WN) * 32;
    constexpr int SA = BM * 128;
    constexpr int SB = BN * 128;
    constexpr int STAGE = 2 * SA + 2 * SB;
    constexpr int NCHUNK = HH / 64;

    extern __shared__ char smem[];
    const uint32_t sbase = smem_u32(smem);
    const int tid = threadIdx.x;
    const int wid = tid >> 5, lane = tid & 31;
    const size_t bm = (size_t)blockIdx.y * BM;
    const int bn = blockIdx.x * BN;
    const int wm = (wid % (BM / WM)) * WM;
    const int wn = (wid / (BM / WM)) * WN;

    float acc[WM / 16][WN / 8][4];
#pragma unroll
    for (int mi = 0; mi < WM / 16; ++mi)
#pragma unroll
        for (int ni = 0; ni < WN / 8; ++ni)
#pragma unroll
            for (int q = 0; q < 4; ++q) acc[mi][ni][q] = 0.0f;

    const int sub = lane >> 3, li = lane & 7;
    const int arow = (sub & 1) * 8 + li;
    const int akb  = (sub >> 1) * 16;
    const int brow = (sub >> 1) * 8 + li;
    const int bkb  = (sub & 1) * 16;
    const uint32_t swx = (uint32_t)(li * 16);

    auto issue_loads = [&](int c, int s) {
        const uint32_t st = sbase + (uint32_t)(s * STAGE);
        const int kb = c * 64;
        load_tile_async<BM, THREADS>(Ahi, bm, kb, st, tid);
        load_tile_async<BM, THREADS>(Alo, bm, kb, st + SA, tid);
        load_tile_async<BN, THREADS>(Bhi, (size_t)bn, kb, st + 2 * SA, tid);
        load_tile_async<BN, THREADS>(Blo, (size_t)bn, kb, st + 2 * SA + SB, tid);
        CP_COMMIT();
    };

    issue_loads(0, 0);

    for (int c = 0; c < NCHUNK; ++c) {
        if (c + 1 < NCHUNK) {
            issue_loads(c + 1, (c + 1) & 1);
            CP_WAIT(1);
        } else {
            CP_WAIT(0);
        }
        __syncthreads();

        const uint32_t st = sbase + (uint32_t)((c & 1) * STAGE);
        const uint32_t aHi = st + (uint32_t)((wm + arow) * 128);
        const uint32_t aLo = aHi + SA;
        const uint32_t bHi = st + 2 * SA + (uint32_t)((wn + brow) * 128);
        const uint32_t bLo = bHi + SB;

#pragma unroll
        for (int kk = 0; kk < 4; ++kk) {
            const uint32_t ka = (uint32_t)(kk * 32 + akb) ^ swx;
            const uint32_t kb2 = (uint32_t)(kk * 32 + bkb) ^ swx;
            uint32_t ah[WM / 16][4], al[WM / 16][4], bh[WN / 16][4], bl[WN / 16][4];
#pragma unroll
            for (int mi = 0; mi < WM / 16; ++mi) {
                ldsm4(ah[mi], aHi + mi * 2048 + ka);
                ldsm4(al[mi], aLo + mi * 2048 + ka);
            }
#pragma unroll
            for (int nj = 0; nj < WN / 16; ++nj) {
                ldsm4(bh[nj], bHi + nj * 2048 + kb2);
                ldsm4(bl[nj], bLo + nj * 2048 + kb2);
            }
#pragma unroll
            for (int mi = 0; mi < WM / 16; ++mi)
#pragma unroll
                for (int ni = 0; ni < WN / 8; ++ni)
                    mma16816(acc[mi][ni], ah[mi],
                             bh[ni >> 1][2 * (ni & 1)], bh[ni >> 1][2 * (ni & 1) + 1]);
#pragma unroll
            for (int mi = 0; mi < WM / 16; ++mi)
#pragma unroll
                for (int ni = 0; ni < WN / 8; ++ni)
                    mma16816(acc[mi][ni], ah[mi],
                             bl[ni >> 1][2 * (ni & 1)], bl[ni >> 1][2 * (ni & 1) + 1]);
#pragma unroll
            for (int mi = 0; mi < WM / 16; ++mi)
#pragma unroll
                for (int ni = 0; ni < WN / 8; ++ni)
                    mma16816(acc[mi][ni], al[mi],
                             bh[ni >> 1][2 * (ni & 1)], bh[ni >> 1][2 * (ni & 1) + 1]);
        }
        __syncthreads();
    }

    const int g = lane >> 2, tg = lane & 3;
#pragma unroll
    for (int mi = 0; mi < WM / 16; ++mi) {
#pragma unroll
        for (int ni = 0; ni < WN / 8; ++ni) {
            const size_t r0 = bm + (size_t)(wm + mi * 16 + g);
            const size_t r1 = r0 + 8;
            const int c0 = bn + wn + ni * 8 + 2 * tg;
            float b0 = bih[c0] + bhh[c0];
            float b1 = bih[c0 + 1] + bhh[c0 + 1];
            *(float2*)(out_f + r0 * HH + c0) =
                make_float2(acc[mi][ni][0] + b0, acc[mi][ni][1] + b1);
            *(float2*)(out_f + r1 * HH + c0) =
                make_float2(acc[mi][ni][2] + b0, acc[mi][ni][3] + b1);
        }
    }
}

// -------------------- persistent recurrence kernel -------------------------
// 128 CTAs (one/SM, all resident), 128 threads. Tile 32(M)x64(N), W_hh hi/lo
// resident in smem for all 511 steps. Grid barrier between steps.
#define NCTA 128
#define PBM 32
#define PBN 64
// smem map
#define SMB 0                       // W_hh: hi [0,64K), lo [64K,128K); chunk stride 8K
#define SMB_SPLIT 65536
#define SMB_CHUNK 8192
#define SMA 131072                  // A (h): 3 bufs x 8K (hi +0, lo +4096)
#define SMA_BUF 8192
#define SMXP 155648                 // xp tile: 32x64 f32 = 8K
#define PSMEM 163840

__device__ __forceinline__ void grid_barrier(int tid, unsigned target) {
    __threadfence();
    __syncthreads();
    if (tid == 0) {
        unsigned a = atomicAdd(&g_bar_count, 1u);
        if (a == NCTA - 1) {
            g_bar_count = 0;
            __threadfence();
            g_bar_phase = target;
        } else {
            while ((int)(g_bar_phase - target) < 0) { }
        }
        __threadfence();
    }
    __syncthreads();
}

__global__ void __launch_bounds__(128, 1)
rnn_persistent_kernel(const float* __restrict__ xp,
                      const __nv_bfloat16* __restrict__ whh_h,
                      const __nv_bfloat16* __restrict__ whh_l,
                      __nv_bfloat16* __restrict__ hhi, __nv_bfloat16* __restrict__ hlo,
                      float* __restrict__ out)
{
    extern __shared__ char smem[];
    const uint32_t sb = smem_u32(smem);
    const int tid = threadIdx.x;
    const int wid = tid >> 5, lane = tid & 31;
    const int mtile = blockIdx.x >> 3;      // 0..15
    const int ntile = blockIdx.x & 7;       // 0..7
    const size_t bm = (size_t)mtile * PBM;
    const int bn = ntile * PBN;
    const int wm = (wid & 1) * 16;          // 2x2 warp grid: WM=16, WN=32
    const int wn = (wid >> 1) * 32;

    unsigned phase0 = 0;
    if (tid == 0) phase0 = g_bar_phase;

    // ---- load resident W_hh tiles (rows bn..bn+64, all K), both splits ----
#pragma unroll
    for (int i = 0; i < 64; ++i) {
        int v = i * 128 + tid;              // 8192 granules
        int split = v >> 12;
        int rem = v & 4095;
        int chunk = rem >> 9;
        int rr = rem & 511;
        int row = rr >> 3, g16 = rr & 7;
        const __nv_bfloat16* src = (split ? whh_l : whh_h);
        uint32_t dst = sb + SMB + split * SMB_SPLIT + chunk * SMB_CHUNK
                     + row * 128 + (uint32_t)((g16 * 16) ^ ((row & 7) * 16));
        cp16(dst, src + (size_t)(bn + row) * HH + chunk * 64 + g16 * 8);
    }
    CP_COMMIT();

    // ---- step 0: h1 = tanh(xp_0) for this tile (overlaps W load) ----------
#pragma unroll
    for (int i = 0; i < 4; ++i) {
        int v = i * 128 + tid;              // 512 float4 granules
        int row = v >> 4, c4 = v & 15;
        const float4 x = *(const float4*)(xp + (bm + row) * HH + bn + c4 * 4);
        float v0 = tanhf(x.x), v1 = tanhf(x.y), v2 = tanhf(x.z), v3 = tanhf(x.w);
        __nv_bfloat16 h0, l0, h1, l1, h2, l2, h3, l3;
        split1(v0, h0, l0); split1(v1, h1, l1);
        split1(v2, h2, l2); split1(v3, h3, l3);
        __nv_bfloat162 hp0(h0, h1), hp1(h2, h3), lp0(l0, l1), lp1(l2, l3);
        size_t off = (bm + row) * HH + bn + c4 * 4;
        *(uint2*)(hhi + off) = make_uint2(*(uint32_t*)&hp0, *(uint32_t*)&hp1);
        *(uint2*)(hlo + off) = make_uint2(*(uint32_t*)&lp0, *(uint32_t*)&lp1);
    }
    CP_WAIT(0);
    grid_barrier(tid, phase0 + 1);

    // ldmatrix lane geometry
    const int sub = lane >> 3, li = lane & 7;
    const int arow = (sub & 1) * 8 + li;
    const int akb  = (sub >> 1) * 16;
    const int brow = (sub >> 1) * 8 + li;
    const int bkb  = (sub & 1) * 16;
    const uint32_t swx = (uint32_t)(li * 16);
    const int g = lane >> 2, tg = lane & 3;

    for (int t = 1; t < TT; ++t) {
        const __nv_bfloat16* Ah = hhi + (size_t)((t - 1) & 1) * BH;
        const __nv_bfloat16* Al = hlo + (size_t)((t - 1) & 1) * BH;
        const float* xpt = xp + (size_t)t * BH;

        // issue an A chunk (hi+lo) into buffer b
        auto issueA = [&](int c, int b) {
            const uint32_t base = sb + SMA + b * SMA_BUF;
#pragma unroll
            for (int i = 0; i < 4; ++i) {
                int v = i * 128 + tid;       // 512 granules
                int split = v >> 8;
                int rr = v & 255;
                int row = rr >> 3, g16 = rr & 7;
                const __nv_bfloat16* src = (split ? Al : Ah);
                uint32_t dst = base + split * 4096 + row * 128
                             + (uint32_t)((g16 * 16) ^ ((row & 7) * 16));
                cp16(dst, src + (bm + (size_t)row) * HH + c * 64 + g16 * 8);
            }
        };

        // G0: xp tile + A chunk 0
        {
#pragma unroll
            for (int i = 0; i < 4; ++i) {
                int v = i * 128 + tid;       // 512 granules of 16B (32x64 f32)
                int row = v >> 4, g16 = v & 15;
                cp16(sb + SMXP + row * 256 + g16 * 16,
                     xpt + (bm + row) * HH + bn + g16 * 4);
            }
            issueA(0, 0);
            CP_COMMIT();
        }
        issueA(1, 1);
        CP_COMMIT();

        float acc[4][4];
#pragma unroll
        for (int ni = 0; ni < 4; ++ni)
#pragma unroll
            for (int q = 0; q < 4; ++q) acc[ni][q] = 0.0f;

#pragma unroll
        for (int c = 0; c < 8; ++c) {
            if (c < 7) { CP_WAIT(1); } else { CP_WAIT(0); }
            __syncthreads();
            if (c + 2 <= 7) {  // 3-stage A buffering: safe to issue before compute
                issueA(c + 2, (c + 2) % 3);
                CP_COMMIT();
            }

            const uint32_t aBase = sb + SMA + (c % 3) * SMA_BUF;
            const uint32_t aHi = aBase + (uint32_t)((wm + arow) * 128);
            const uint32_t aLo = aHi + 4096;
            const uint32_t bHi = sb + SMB + c * SMB_CHUNK + (uint32_t)((wn + brow) * 128);
            const uint32_t bLo = bHi + SMB_SPLIT;

#pragma unroll
            for (int kk = 0; kk < 4; ++kk) {
                const uint32_t ka  = (uint32_t)(kk * 32 + akb) ^ swx;
                const uint32_t kb2 = (uint32_t)(kk * 32 + bkb) ^ swx;
                uint32_t ah[4], al4[4], bh[2][4], bl[2][4];
                ldsm4(ah, aHi + ka);
                ldsm4(al4, aLo + ka);
                ldsm4(bh[0], bHi + kb2);
                ldsm4(bh[1], bHi + 2048 + kb2);
                ldsm4(bl[0], bLo + kb2);
                ldsm4(bl[1], bLo + 2048 + kb2);
#pragma unroll
                for (int ni = 0; ni < 4; ++ni)
                    mma16816(acc[ni], ah, bh[ni >> 1][2 * (ni & 1)], bh[ni >> 1][2 * (ni & 1) + 1]);
#pragma unroll
                for (int ni = 0; ni < 4; ++ni)
                    mma16816(acc[ni], ah, bl[ni >> 1][2 * (ni & 1)], bl[ni >> 1][2 * (ni & 1) + 1]);
#pragma unroll
                for (int ni = 0; ni < 4; ++ni)
                    mma16816(acc[ni], al4, bh[ni >> 1][2 * (ni & 1)], bh[ni >> 1][2 * (ni & 1) + 1]);
            }
        }

        // epilogue: tanh(acc + xp), write next h (or final out)
        __nv_bfloat16* oh = hhi + (size_t)(t & 1) * BH;
        __nv_bfloat16* ol = hlo + (size_t)(t & 1) * BH;
        const float* sXP = (const float*)(smem + SMXP);
#pragma unroll
        for (int ni = 0; ni < 4; ++ni) {
            const int lr0 = wm + g;
            const int lc  = wn + ni * 8 + 2 * tg;
            const size_t r0 = bm + (size_t)lr0;
            const size_t r1 = r0 + 8;
            const int c0 = bn + lc;
            float2 x0 = *(const float2*)(sXP + lr0 * PBN + lc);
            float2 x1 = *(const float2*)(sXP + (lr0 + 8) * PBN + lc);
            float v0 = tanhf(acc[ni][0] + x0.x);
            float v1 = tanhf(acc[ni][1] + x0.y);
            float v2 = tanhf(acc[ni][2] + x1.x);
            float v3 = tanhf(acc[ni][3] + x1.y);
            if (t == TT - 1) {
                *(float2*)(out + r0 * HH + c0) = make_float2(v0, v1);
                *(float2*)(out + r1 * HH + c0) = make_float2(v2, v3);
            } else {
                __nv_bfloat16 h0, l0, h1, l1, h2, l2, h3, l3;
                split1(v0, h0, l0); split1(v1, h1, l1);
                split1(v2, h2, l2); split1(v3, h3, l3);
                __nv_bfloat162 hp0(h0, h1), hp1(h2, h3), lp0(l0, l1), lp1(l2, l3);
                *(uint32_t*)(oh + r0 * HH + c0) = *(uint32_t*)&hp0;
                *(uint32_t*)(ol + r0 * HH + c0) = *(uint32_t*)&lp0;
                *(uint32_t*)(oh + r1 * HH + c0) = *(uint32_t*)&hp1;
                *(uint32_t*)(ol + r1 * HH + c0) = *(uint32_t*)&lp1;
            }
        }

        if (t < TT - 1) grid_barrier(tid, phase0 + 1 + (unsigned)t);
    }
}

// -------------------- launcher ---------------------------------------------
extern "C" void kernel_launch(void* const* d_in, const int* in_sizes, int n_in,
                              void* d_out, int out_size)
{
    const float* X   = (const float*)d_in[0];
    const float* Wih = (const float*)d_in[1];
    const float* Whh = (const float*)d_in[2];
    const float* bih = (const float*)d_in[3];
    const float* bhh = (const float*)d_in[4];
    float* out = (float*)d_out;

    float* xp;
    __nv_bfloat16 *xhi, *xlo, *wih_h, *wih_l, *whh_h, *whh_l, *hhi, *hlo;
    cudaGetSymbolAddress((void**)&xp, g_xp);
    cudaGetSymbolAddress((void**)&xhi, g_xhi);
    cudaGetSymbolAddress((void**)&xlo, g_xlo);
    cudaGetSymbolAddress((void**)&wih_h, g_wih_h);
    cudaGetSymbolAddress((void**)&wih_l, g_wih_l);
    cudaGetSymbolAddress((void**)&whh_h, g_whh_h);
    cudaGetSymbolAddress((void**)&whh_l, g_whh_l);
    cudaGetSymbolAddress((void**)&hhi, g_hhi);
    cudaGetSymbolAddress((void**)&hlo, g_hlo);

    constexpr int SMEM_XP = 2 * (2 * 128 * 128 + 2 * 128 * 128);  // 131072
    cudaFuncSetAttribute(gemm_split_kernel<128, 128, 64, 32, false>,
                         cudaFuncAttributeMaxDynamicSharedMemorySize, SMEM_XP);
    cudaFuncSetAttribute(rnn_persistent_kernel,
                         cudaFuncAttributeMaxDynamicSharedMemorySize, PSMEM);

    // 1) hi/lo splits
    split_kernel<<<128, 256>>>(Wih, wih_h, wih_l, HH * DD / 4);
    split_kernel<<<128, 256>>>(Whh, whh_h, whh_l, HH * HH / 4);
    split_kernel<<<8192, 256>>>(X, xhi, xlo, (int)((size_t)TT * BB * DD / 4));

    // 2) xp = X @ Wih^T + (b_ih + b_hh) for all timesteps
    {
        dim3 g(HH / 128, (TT * BB) / 128);
        gemm_split_kernel<128, 128, 64, 32, false><<<g, 256, SMEM_XP>>>(
            xhi, xlo, wih_h, wih_l, nullptr, bih, bhh, xp, nullptr, nullptr);
    }

    // 3) entire recurrence in one persistent kernel
    rnn_persistent_kernel<<<NCTA, 128, PSMEM>>>(xp, whh_h, whh_l, hhi, hlo, out);
}

// round 5
// speedup vs baseline: 4.6951x; 1.0187x over previous
#include <cuda_runtime.h>
#include <cuda_bf16.h>
#include <math.h>
#include <stdint.h>

// Problem dims (fixed)
#define TT 512
#define BB 512
#define DD 512
#define HH 512
#define BH (BB * HH)  // 262144

// -------------------- device scratch (no allocations allowed) --------------
__device__ float          g_xp[(size_t)TT * BH];            // 512 MB
__device__ __nv_bfloat16  g_xhi[(size_t)TT * BB * DD];      // 256 MB
__device__ __nv_bfloat16  g_xlo[(size_t)TT * BB * DD];      // 256 MB
__device__ __nv_bfloat16  g_wih_h[HH * DD], g_wih_l[HH * DD];
__device__ __nv_bfloat16  g_whh_h[HH * HH], g_whh_l[HH * HH];
__device__ __nv_bfloat16  g_hhi[2][BH], g_hlo[2][BH];

// per-row-group barrier state (16 row groups, 128B stride to avoid collisions)
// cnt returns to 0 at every barrier; flag increments exactly once per barrier
// (deterministic count per launch -> graph-replay safe).
__device__ unsigned g_row_cnt[16 * 32];
__device__ volatile unsigned g_row_flag[16 * 32];

// -------------------- PTX helpers (sm_80-level only; no 'a' features) ------
__device__ __forceinline__ uint32_t smem_u32(const void* p) {
    uint32_t a;
    asm("{ .reg .u64 t; cvta.to.shared.u64 t, %1; cvt.u32.u64 %0, t; }" : "=r"(a) : "l"(p));
    return a;
}
__device__ __forceinline__ void cp16(uint32_t s, const void* g) {
    asm volatile("cp.async.cg.shared.global [%0], [%1], 16;" :: "r"(s), "l"(g));
}
#define CP_COMMIT() asm volatile("cp.async.commit_group;" ::: "memory")
#define CP_WAIT(n)  asm volatile("cp.async.wait_group %0;" :: "n"(n) : "memory")

__device__ __forceinline__ void ldsm4(uint32_t* r, uint32_t addr) {
    asm volatile("ldmatrix.sync.aligned.m8n8.x4.shared.b16 {%0,%1,%2,%3}, [%4];"
                 : "=r"(r[0]), "=r"(r[1]), "=r"(r[2]), "=r"(r[3]) : "r"(addr));
}
__device__ __forceinline__ void mma16816(float* d, const uint32_t* a, uint32_t b0, uint32_t b1) {
    asm volatile("mma.sync.aligned.m16n8k16.row.col.f32.bf16.bf16.f32 "
                 "{%0,%1,%2,%3}, {%4,%5,%6,%7}, {%8,%9}, {%0,%1,%2,%3};"
                 : "+f"(d[0]), "+f"(d[1]), "+f"(d[2]), "+f"(d[3])
                 : "r"(a[0]), "r"(a[1]), "r"(a[2]), "r"(a[3]), "r"(b0), "r"(b1));
}

// -------------------- split helpers ----------------------------------------
__device__ __forceinline__ void split1(float x, __nv_bfloat16& h, __nv_bfloat16& l) {
    h = __float2bfloat16_rn(x);
    l = __float2bfloat16_rn(x - __bfloat162float(h));
}

__global__ __launch_bounds__(256) void split_kernel(const float* __restrict__ src,
                                                    __nv_bfloat16* __restrict__ hi,
                                                    __nv_bfloat16* __restrict__ lo, int n4) {
    for (int i = blockIdx.x * blockDim.x + threadIdx.x; i < n4; i += gridDim.x * blockDim.x) {
        float4 v = ((const float4*)src)[i];
        __nv_bfloat16 h0, h1, h2, h3, l0, l1, l2, l3;
        split1(v.x, h0, l0); split1(v.y, h1, l1);
        split1(v.z, h2, l2); split1(v.w, h3, l3);
        __nv_bfloat162* ph = (__nv_bfloat162*)hi;
        __nv_bfloat162* pl = (__nv_bfloat162*)lo;
        ph[i * 2] = __nv_bfloat162(h0, h1); ph[i * 2 + 1] = __nv_bfloat162(h2, h3);
        pl[i * 2] = __nv_bfloat162(l0, l1); pl[i * 2 + 1] = __nv_bfloat162(l2, l3);
    }
}

// -------------------- async tile loader (generic, 64-col bf16 tiles) -------
template <int ROWS, int THREADS>
__device__ __forceinline__ void load_tile_async(const __nv_bfloat16* __restrict__ g,
                                                size_t row0, int kbase,
                                                uint32_t sdst, int tid) {
    constexpr int TOT = ROWS * 8;  // 16B granules
#pragma unroll
    for (int i = 0; i < TOT / THREADS; ++i) {
        int v = i * THREADS + tid;
        int row = v >> 3, g16 = v & 7;
        uint32_t off = (uint32_t)(row * 128 + ((g16 * 16) ^ ((row & 7) * 16)));
        cp16(sdst + off, g + (row0 + (size_t)row) * HH + kbase + g16 * 8);
    }
}

// -------------------- xp GEMM (proven; IS_STEP=false path only) ------------
template <int BM, int BN, int WM, int WN, bool IS_STEP>
__global__ void __launch_bounds__((BM / WM) * (BN / WN) * 32, 1)
gemm_split_kernel(const __nv_bfloat16* __restrict__ Ahi, const __nv_bfloat16* __restrict__ Alo,
                  const __nv_bfloat16* __restrict__ Bhi, const __nv_bfloat16* __restrict__ Blo,
                  const float* __restrict__ xp_t,
                  const float* __restrict__ bih, const float* __restrict__ bhh,
                  float* __restrict__ out_f,
                  __nv_bfloat16* __restrict__ out_hi, __nv_bfloat16* __restrict__ out_lo)
{
    constexpr int THREADS = (BM / WM) * (BN / WN) * 32;
    constexpr int SA = BM * 128;
    constexpr int SB = BN * 128;
    constexpr int STAGE = 2 * SA + 2 * SB;
    constexpr int NCHUNK = HH / 64;

    extern __shared__ char smem[];
    const uint32_t sbase = smem_u32(smem);
    const int tid = threadIdx.x;
    const int wid = tid >> 5, lane = tid & 31;
    const size_t bm = (size_t)blockIdx.y * BM;
    const int bn = blockIdx.x * BN;
    const int wm = (wid % (BM / WM)) * WM;
    const int wn = (wid / (BM / WM)) * WN;

    float acc[WM / 16][WN / 8][4];
#pragma unroll
    for (int mi = 0; mi < WM / 16; ++mi)
#pragma unroll
        for (int ni = 0; ni < WN / 8; ++ni)
#pragma unroll
            for (int q = 0; q < 4; ++q) acc[mi][ni][q] = 0.0f;

    const int sub = lane >> 3, li = lane & 7;
    const int arow = (sub & 1) * 8 + li;
    const int akb  = (sub >> 1) * 16;
    const int brow = (sub >> 1) * 8 + li;
    const int bkb  = (sub & 1) * 16;
    const uint32_t swx = (uint32_t)(li * 16);

    auto issue_loads = [&](int c, int s) {
        const uint32_t st = sbase + (uint32_t)(s * STAGE);
        const int kb = c * 64;
        load_tile_async<BM, THREADS>(Ahi, bm, kb, st, tid);
        load_tile_async<BM, THREADS>(Alo, bm, kb, st + SA, tid);
        load_tile_async<BN, THREADS>(Bhi, (size_t)bn, kb, st + 2 * SA, tid);
        load_tile_async<BN, THREADS>(Blo, (size_t)bn, kb, st + 2 * SA + SB, tid);
        CP_COMMIT();
    };

    issue_loads(0, 0);

    for (int c = 0; c < NCHUNK; ++c) {
        if (c + 1 < NCHUNK) {
            issue_loads(c + 1, (c + 1) & 1);
            CP_WAIT(1);
        } else {
            CP_WAIT(0);
        }
        __syncthreads();

        const uint32_t st = sbase + (uint32_t)((c & 1) * STAGE);
        const uint32_t aHi = st + (uint32_t)((wm + arow) * 128);
        const uint32_t aLo = aHi + SA;
        const uint32_t bHi = st + 2 * SA + (uint32_t)((wn + brow) * 128);
        const uint32_t bLo = bHi + SB;

#pragma unroll
        for (int kk = 0; kk < 4; ++kk) {
            const uint32_t ka = (uint32_t)(kk * 32 + akb) ^ swx;
            const uint32_t kb2 = (uint32_t)(kk * 32 + bkb) ^ swx;
            uint32_t ah[WM / 16][4], al[WM / 16][4], bh[WN / 16][4], bl[WN / 16][4];
#pragma unroll
            for (int mi = 0; mi < WM / 16; ++mi) {
                ldsm4(ah[mi], aHi + mi * 2048 + ka);
                ldsm4(al[mi], aLo + mi * 2048 + ka);
            }
#pragma unroll
            for (int nj = 0; nj < WN / 16; ++nj) {
                ldsm4(bh[nj], bHi + nj * 2048 + kb2);
                ldsm4(bl[nj], bLo + nj * 2048 + kb2);
            }
#pragma unroll
            for (int mi = 0; mi < WM / 16; ++mi)
#pragma unroll
                for (int ni = 0; ni < WN / 8; ++ni)
                    mma16816(acc[mi][ni], ah[mi],
                             bh[ni >> 1][2 * (ni & 1)], bh[ni >> 1][2 * (ni & 1) + 1]);
#pragma unroll
            for (int mi = 0; mi < WM / 16; ++mi)
#pragma unroll
                for (int ni = 0; ni < WN / 8; ++ni)
                    mma16816(acc[mi][ni], ah[mi],
                             bl[ni >> 1][2 * (ni & 1)], bl[ni >> 1][2 * (ni & 1) + 1]);
#pragma unroll
            for (int mi = 0; mi < WM / 16; ++mi)
#pragma unroll
                for (int ni = 0; ni < WN / 8; ++ni)
                    mma16816(acc[mi][ni], al[mi],
                             bh[ni >> 1][2 * (ni & 1)], bh[ni >> 1][2 * (ni & 1) + 1]);
        }
        __syncthreads();
    }

    const int g = lane >> 2, tg = lane & 3;
#pragma unroll
    for (int mi = 0; mi < WM / 16; ++mi) {
#pragma unroll
        for (int ni = 0; ni < WN / 8; ++ni) {
            const size_t r0 = bm + (size_t)(wm + mi * 16 + g);
            const size_t r1 = r0 + 8;
            const int c0 = bn + wn + ni * 8 + 2 * tg;
            float b0 = bih[c0] + bhh[c0];
            float b1 = bih[c0 + 1] + bhh[c0 + 1];
            *(float2*)(out_f + r0 * HH + c0) =
                make_float2(acc[mi][ni][0] + b0, acc[mi][ni][1] + b1);
            *(float2*)(out_f + r1 * HH + c0) =
                make_float2(acc[mi][ni][2] + b0, acc[mi][ni][3] + b1);
        }
    }
}

// -------------------- persistent recurrence kernel -------------------------
// 128 CTAs (one/SM), 256 threads. CTA tile 32(M)x64(N). W_hh resident in smem.
// All 8 A chunks + xp preloaded per step. Row-local 8-CTA barriers.
#define NCTA 128
#define PBM 32
#define PBN 64
// smem map
#define SMB 0                       // W_hh: hi [0,64K), lo [64K,128K); chunk stride 8K
#define SMB_SPLIT 65536
#define SMB_CHUNK 8192
#define SMA 131072                  // A (h): 8 chunks x 8K (hi +0, lo +4096)
#define SMA_CHUNK 8192
#define SMXP 196608                 // xp tile: 32x64 f32 = 8K
#define PSMEM 204800

__device__ __forceinline__ void row_barrier(int tid, int m, unsigned target) {
    __syncthreads();
    if (tid == 0) {
        __threadfence();                      // release this CTA's h writes
        unsigned old = atomicAdd(&g_row_cnt[m * 32], 1u);
        if (old == 7u) {
            atomicExch(&g_row_cnt[m * 32], 0u);
            __threadfence();
            atomicAdd((unsigned*)&g_row_flag[m * 32], 1u);
        } else {
            while ((int)(g_row_flag[m * 32] - target) < 0) { }
        }
        __threadfence();                      // acquire peers' h writes
    }
    __syncthreads();
}

__global__ void __launch_bounds__(256, 1)
rnn_persistent_kernel(const float* __restrict__ xp,
                      const __nv_bfloat16* __restrict__ whh_h,
                      const __nv_bfloat16* __restrict__ whh_l,
                      __nv_bfloat16* __restrict__ hhi, __nv_bfloat16* __restrict__ hlo,
                      float* __restrict__ out)
{
    extern __shared__ char smem[];
    const uint32_t sb = smem_u32(smem);
    const int tid = threadIdx.x;
    const int wid = tid >> 5, lane = tid & 31;
    const int mtile = blockIdx.x >> 3;      // 0..15
    const int ntile = blockIdx.x & 7;       // 0..7
    const size_t bm = (size_t)mtile * PBM;
    const int bn = ntile * PBN;
    const int wm = (wid & 1) * 16;          // 2x4 warp grid: WM=16, WN=16
    const int wn = (wid >> 1) * 16;

    // flag base: safe to read before this CTA's first arrival (flag cannot
    // advance past base until THIS CTA arrives). Only tid 0 uses it.
    unsigned rowbase = 0;
    if (tid == 0) rowbase = g_row_flag[mtile * 32];

    // ---- load resident W_hh tiles (rows bn..bn+64, all K), both splits ----
#pragma unroll
    for (int i = 0; i < 32; ++i) {
        int v = i * 256 + tid;              // 8192 granules
        int split = v >> 12;
        int rem = v & 4095;
        int chunk = rem >> 9;
        int rr = rem & 511;
        int row = rr >> 3, g16 = rr & 7;
        const __nv_bfloat16* src = (split ? whh_l : whh_h);
        uint32_t dst = sb + SMB + split * SMB_SPLIT + chunk * SMB_CHUNK
                     + row * 128 + (uint32_t)((g16 * 16) ^ ((row & 7) * 16));
        cp16(dst, src + (size_t)(bn + row) * HH + chunk * 64 + g16 * 8);
    }
    CP_COMMIT();

    // ---- step 0: h1 = tanh(xp_0) for this tile (overlaps W load) ----------
#pragma unroll
    for (int i = 0; i < 2; ++i) {
        int v = i * 256 + tid;              // 512 float4 granules
        int row = v >> 4, c4 = v & 15;
        const float4 x = *(const float4*)(xp + (bm + row) * HH + bn + c4 * 4);
        float v0 = tanhf(x.x), v1 = tanhf(x.y), v2 = tanhf(x.z), v3 = tanhf(x.w);
        __nv_bfloat16 h0, l0, h1, l1, h2, l2, h3, l3;
        split1(v0, h0, l0); split1(v1, h1, l1);
        split1(v2, h2, l2); split1(v3, h3, l3);
        __nv_bfloat162 hp0(h0, h1), hp1(h2, h3), lp0(l0, l1), lp1(l2, l3);
        size_t off = (bm + row) * HH + bn + c4 * 4;
        *(uint2*)(hhi + off) = make_uint2(*(uint32_t*)&hp0, *(uint32_t*)&hp1);
        *(uint2*)(hlo + off) = make_uint2(*(uint32_t*)&lp0, *(uint32_t*)&lp1);
    }
    CP_WAIT(0);
    row_barrier(tid, mtile, rowbase + 1);

    // ldmatrix lane geometry
    const int sub = lane >> 3, li = lane & 7;
    const int arow = (sub & 1) * 8 + li;
    const int akb  = (sub >> 1) * 16;
    const int brow = (sub >> 1) * 8 + li;
    const int bkb  = (sub & 1) * 16;
    const uint32_t swx = (uint32_t)(li * 16);
    const int g = lane >> 2, tg = lane & 3;

    for (int t = 1; t < TT; ++t) {
        const __nv_bfloat16* Ah = hhi + (size_t)((t - 1) & 1) * BH;
        const __nv_bfloat16* Al = hlo + (size_t)((t - 1) & 1) * BH;
        const float* xpt = xp + (size_t)t * BH;

        auto issueA = [&](int c) {
            const uint32_t base = sb + SMA + c * SMA_CHUNK;
#pragma unroll
            for (int i = 0; i < 2; ++i) {
                int v = i * 256 + tid;       // 512 granules (hi 256 + lo 256)
                int split = v >> 8;
                int rr = v & 255;
                int row = rr >> 3, g16 = rr & 7;
                const __nv_bfloat16* src = (split ? Al : Ah);
                uint32_t dst = base + split * 4096 + row * 128
                             + (uint32_t)((g16 * 16) ^ ((row & 7) * 16));
                cp16(dst, src + (bm + (size_t)row) * HH + c * 64 + g16 * 8);
            }
        };

        // group 0: xp tile + A chunk 0; groups 1..7: A chunks 1..7
        {
#pragma unroll
            for (int i = 0; i < 2; ++i) {
                int v = i * 256 + tid;       // 512 granules (32x64 f32)
                int row = v >> 4, g16 = v & 15;
                cp16(sb + SMXP + row * 256 + g16 * 16,
                     xpt + (bm + row) * HH + bn + g16 * 4);
            }
            issueA(0);
            CP_COMMIT();
        }
#pragma unroll
        for (int c = 1; c < 8; ++c) { issueA(c); CP_COMMIT(); }

        float acc[2][4];
#pragma unroll
        for (int ni = 0; ni < 2; ++ni)
#pragma unroll
            for (int q = 0; q < 4; ++q) acc[ni][q] = 0.0f;

#pragma unroll
        for (int cc = 0; cc < 8; cc += 2) {
            if (cc == 0)      { CP_WAIT(6); }
            else if (cc == 2) { CP_WAIT(4); }
            else if (cc == 4) { CP_WAIT(2); }
            else              { CP_WAIT(0); }
            __syncthreads();

#pragma unroll
            for (int cd = 0; cd < 2; ++cd) {
                const int c = cc + cd;
                const uint32_t aHi = sb + SMA + c * SMA_CHUNK + (uint32_t)((wm + arow) * 128);
                const uint32_t aLo = aHi + 4096;
                const uint32_t bHi = sb + SMB + c * SMB_CHUNK + (uint32_t)((wn + brow) * 128);
                const uint32_t bLo = bHi + SMB_SPLIT;

#pragma unroll
                for (int kk = 0; kk < 4; ++kk) {
                    const uint32_t ka  = (uint32_t)(kk * 32 + akb) ^ swx;
                    const uint32_t kb2 = (uint32_t)(kk * 32 + bkb) ^ swx;
                    uint32_t ah[4], al4[4], bh[4], bl[4];
                    ldsm4(ah, aHi + ka);
                    ldsm4(al4, aLo + ka);
                    ldsm4(bh, bHi + kb2);
                    ldsm4(bl, bLo + kb2);
#pragma unroll
                    for (int ni = 0; ni < 2; ++ni)
                        mma16816(acc[ni], ah, bh[2 * ni], bh[2 * ni + 1]);
#pragma unroll
                    for (int ni = 0; ni < 2; ++ni)
                        mma16816(acc[ni], ah, bl[2 * ni], bl[2 * ni + 1]);
#pragma unroll
                    for (int ni = 0; ni < 2; ++ni)
                        mma16816(acc[ni], al4, bh[2 * ni], bh[2 * ni + 1]);
                }
            }
        }

        // epilogue: tanh(acc + xp), write next h (or final out)
        __nv_bfloat16* oh = hhi + (size_t)(t & 1) * BH;
        __nv_bfloat16* ol = hlo + (size_t)(t & 1) * BH;
        const float* sXP = (const float*)(smem + SMXP);
#pragma unroll
        for (int ni = 0; ni < 2; ++ni) {
            const int lr0 = wm + g;
            const int lc  = wn + ni * 8 + 2 * tg;
            const size_t r0 = bm + (size_t)lr0;
            const size_t r1 = r0 + 8;
            const int c0 = bn + lc;
            float2 x0 = *(const float2*)(sXP + lr0 * PBN + lc);
            float2 x1 = *(const float2*)(sXP + (lr0 + 8) * PBN + lc);
            float v0 = tanhf(acc[ni][0] + x0.x);
            float v1 = tanhf(acc[ni][1] + x0.y);
            float v2 = tanhf(acc[ni][2] + x1.x);
            float v3 = tanhf(acc[ni][3] + x1.y);
            if (t == TT - 1) {
                *(float2*)(out + r0 * HH + c0) = make_float2(v0, v1);
                *(float2*)(out + r1 * HH + c0) = make_float2(v2, v3);
            } else {
                __nv_bfloat16 h0, l0, h1, l1, h2, l2, h3, l3;
                split1(v0, h0, l0); split1(v1, h1, l1);
                split1(v2, h2, l2); split1(v3, h3, l3);
                __nv_bfloat162 hp0(h0, h1), hp1(h2, h3), lp0(l0, l1), lp1(l2, l3);
                *(uint32_t*)(oh + r0 * HH + c0) = *(uint32_t*)&hp0;
                *(uint32_t*)(ol + r0 * HH + c0) = *(uint32_t*)&lp0;
                *(uint32_t*)(oh + r1 * HH + c0) = *(uint32_t*)&hp1;
                *(uint32_t*)(ol + r1 * HH + c0) = *(uint32_t*)&lp1;
            }
        }

        if (t < TT - 1) row_barrier(tid, mtile, rowbase + 1 + (unsigned)t);
    }
}

// -------------------- launcher ---------------------------------------------
extern "C" void kernel_launch(void* const* d_in, const int* in_sizes, int n_in,
                              void* d_out, int out_size)
{
    const float* X   = (const float*)d_in[0];
    const float* Wih = (const float*)d_in[1];
    const float* Whh = (const float*)d_in[2];
    const float* bih = (const float*)d_in[3];
    const float* bhh = (const float*)d_in[4];
    float* out = (float*)d_out;

    float* xp;
    __nv_bfloat16 *xhi, *xlo, *wih_h, *wih_l, *whh_h, *whh_l, *hhi, *hlo;
    cudaGetSymbolAddress((void**)&xp, g_xp);
    cudaGetSymbolAddress((void**)&xhi, g_xhi);
    cudaGetSymbolAddress((void**)&xlo, g_xlo);
    cudaGetSymbolAddress((void**)&wih_h, g_wih_h);
    cudaGetSymbolAddress((void**)&wih_l, g_wih_l);
    cudaGetSymbolAddress((void**)&whh_h, g_whh_h);
    cudaGetSymbolAddress((void**)&whh_l, g_whh_l);
    cudaGetSymbolAddress((void**)&hhi, g_hhi);
    cudaGetSymbolAddress((void**)&hlo, g_hlo);

    constexpr int SMEM_XP = 2 * (2 * 128 * 128 + 2 * 128 * 128);  // 131072
    cudaFuncSetAttribute(gemm_split_kernel<128, 128, 64, 32, false>,
                         cudaFuncAttributeMaxDynamicSharedMemorySize, SMEM_XP);
    cudaFuncSetAttribute(rnn_persistent_kernel,
                         cudaFuncAttributeMaxDynamicSharedMemorySize, PSMEM);

    // 1) hi/lo splits
    split_kernel<<<128, 256>>>(Wih, wih_h, wih_l, HH * DD / 4);
    split_kernel<<<128, 256>>>(Whh, whh_h, whh_l, HH * HH / 4);
    split_kernel<<<8192, 256>>>(X, xhi, xlo, (int)((size_t)TT * BB * DD / 4));

    // 2) xp = X @ Wih^T + (b_ih + b_hh) for all timesteps
    {
        dim3 g(HH / 128, (TT * BB) / 128);
        gemm_split_kernel<128, 128, 64, 32, false><<<g, 256, SMEM_XP>>>(
            xhi, xlo, wih_h, wih_l, nullptr, bih, bhh, xp, nullptr, nullptr);
    }

    // 3) entire recurrence in one persistent kernel (row-local barriers)
    rnn_persistent_kernel<<<NCTA, 256, PSMEM>>>(xp, whh_h, whh_l, hhi, hlo, out);
}

// round 6
// speedup vs baseline: 5.6899x; 1.2119x over previous
#include <cuda_runtime.h>
#include <cuda_bf16.h>
#include <math.h>
#include <stdint.h>

// Problem dims (fixed)
#define TT 512
#define BB 512
#define DD 512
#define HH 512
#define BH (BB * HH)  // 262144

// -------------------- device scratch (no allocations allowed) --------------
__device__ float          g_xp[(size_t)TT * BH];            // 512 MB
__device__ __nv_bfloat16  g_xhi[(size_t)TT * BB * DD];      // 256 MB
__device__ __nv_bfloat16  g_xlo[(size_t)TT * BB * DD];      // 256 MB
__device__ __nv_bfloat16  g_wih_h[HH * DD], g_wih_l[HH * DD];
__device__ __nv_bfloat16  g_whh_h[HH * HH], g_whh_l[HH * HH];
__device__ __nv_bfloat16  g_hhi[2][BH], g_hlo[2][BH];

// producer flags: flag[m][n*32] = monotonic count of h productions by CTA (m,n).
// Each CTA increments exactly 511 times per launch -> all flags stay equal at
// launch boundaries -> own-flag base read is race-free and graph-replay safe.
__device__ unsigned g_flag[16][8 * 32];

// -------------------- PTX helpers (sm_80-level only; no 'a' features) ------
__device__ __forceinline__ uint32_t smem_u32(const void* p) {
    uint32_t a;
    asm("{ .reg .u64 t; cvta.to.shared.u64 t, %1; cvt.u32.u64 %0, t; }" : "=r"(a) : "l"(p));
    return a;
}
__device__ __forceinline__ void cp16(uint32_t s, const void* g) {
    asm volatile("cp.async.cg.shared.global [%0], [%1], 16;" :: "r"(s), "l"(g));
}
#define CP_COMMIT() asm volatile("cp.async.commit_group;" ::: "memory")
#define CP_WAIT(n)  asm volatile("cp.async.wait_group %0;" :: "n"(n) : "memory")

__device__ __forceinline__ void ldsm4(uint32_t* r, uint32_t addr) {
    asm volatile("ldmatrix.sync.aligned.m8n8.x4.shared.b16 {%0,%1,%2,%3}, [%4];"
                 : "=r"(r[0]), "=r"(r[1]), "=r"(r[2]), "=r"(r[3]) : "r"(addr));
}
__device__ __forceinline__ void mma16816(float* d, const uint32_t* a, uint32_t b0, uint32_t b1) {
    asm volatile("mma.sync.aligned.m16n8k16.row.col.f32.bf16.bf16.f32 "
                 "{%0,%1,%2,%3}, {%4,%5,%6,%7}, {%8,%9}, {%0,%1,%2,%3};"
                 : "+f"(d[0]), "+f"(d[1]), "+f"(d[2]), "+f"(d[3])
                 : "r"(a[0]), "r"(a[1]), "r"(a[2]), "r"(a[3]), "r"(b0), "r"(b1));
}

// fast tanh: 1 - 2/(e^{2x}+1) via MUFU (abs err ~1e-6; saturates correctly)
__device__ __forceinline__ float fast_tanh(float x) {
    float e = __expf(2.0f * x);
    return 1.0f - __fdividef(2.0f, e + 1.0f);
}

// -------------------- split helpers ----------------------------------------
__device__ __forceinline__ void split1(float x, __nv_bfloat16& h, __nv_bfloat16& l) {
    h = __float2bfloat16_rn(x);
    l = __float2bfloat16_rn(x - __bfloat162float(h));
}

__global__ __launch_bounds__(256) void split_kernel(const float* __restrict__ src,
                                                    __nv_bfloat16* __restrict__ hi,
                                                    __nv_bfloat16* __restrict__ lo, int n4) {
    for (int i = blockIdx.x * blockDim.x + threadIdx.x; i < n4; i += gridDim.x * blockDim.x) {
        float4 v = ((const float4*)src)[i];
        __nv_bfloat16 h0, h1, h2, h3, l0, l1, l2, l3;
        split1(v.x, h0, l0); split1(v.y, h1, l1);
        split1(v.z, h2, l2); split1(v.w, h3, l3);
        __nv_bfloat162* ph = (__nv_bfloat162*)hi;
        __nv_bfloat162* pl = (__nv_bfloat162*)lo;
        ph[i * 2] = __nv_bfloat162(h0, h1); ph[i * 2 + 1] = __nv_bfloat162(h2, h3);
        pl[i * 2] = __nv_bfloat162(l0, l1); pl[i * 2 + 1] = __nv_bfloat162(l2, l3);
    }
}

// -------------------- async tile loader (generic, 64-col bf16 tiles) -------
template <int ROWS, int THREADS>
__device__ __forceinline__ void load_tile_async(const __nv_bfloat16* __restrict__ g,
                                                size_t row0, int kbase,
                                                uint32_t sdst, int tid) {
    constexpr int TOT = ROWS * 8;  // 16B granules
#pragma unroll
    for (int i = 0; i < TOT / THREADS; ++i) {
        int v = i * THREADS + tid;
        int row = v >> 3, g16 = v & 7;
        uint32_t off = (uint32_t)(row * 128 + ((g16 * 16) ^ ((row & 7) * 16)));
        cp16(sdst + off, g + (row0 + (size_t)row) * HH + kbase + g16 * 8);
    }
}

// -------------------- xp GEMM (proven; IS_STEP=false path only) ------------
template <int BM, int BN, int WM, int WN, bool IS_STEP>
__global__ void __launch_bounds__((BM / WM) * (BN / WN) * 32, 1)
gemm_split_kernel(const __nv_bfloat16* __restrict__ Ahi, const __nv_bfloat16* __restrict__ Alo,
                  const __nv_bfloat16* __restrict__ Bhi, const __nv_bfloat16* __restrict__ Blo,
                  const float* __restrict__ xp_t,
                  const float* __restrict__ bih, const float* __restrict__ bhh,
                  float* __restrict__ out_f,
                  __nv_bfloat16* __restrict__ out_hi, __nv_bfloat16* __restrict__ out_lo)
{
    constexpr int THREADS = (BM / WM) * (BN / WN) * 32;
    constexpr int SA = BM * 128;
    constexpr int SB = BN * 128;
    constexpr int STAGE = 2 * SA + 2 * SB;
    constexpr int NCHUNK = HH / 64;

    extern __shared__ char smem[];
    const uint32_t sbase = smem_u32(smem);
    const int tid = threadIdx.x;
    const int wid = tid >> 5, lane = tid & 31;
    const size_t bm = (size_t)blockIdx.y * BM;
    const int bn = blockIdx.x * BN;
    const int wm = (wid % (BM / WM)) * WM;
    const int wn = (wid / (BM / WM)) * WN;

    float acc[WM / 16][WN / 8][4];
#pragma unroll
    for (int mi = 0; mi < WM / 16; ++mi)
#pragma unroll
        for (int ni = 0; ni < WN / 8; ++ni)
#pragma unroll
            for (int q = 0; q < 4; ++q) acc[mi][ni][q] = 0.0f;

    const int sub = lane >> 3, li = lane & 7;
    const int arow = (sub & 1) * 8 + li;
    const int akb  = (sub >> 1) * 16;
    const int brow = (sub >> 1) * 8 + li;
    const int bkb  = (sub & 1) * 16;
    const uint32_t swx = (uint32_t)(li * 16);

    auto issue_loads = [&](int c, int s) {
        const uint32_t st = sbase + (uint32_t)(s * STAGE);
        const int kb = c * 64;
        load_tile_async<BM, THREADS>(Ahi, bm, kb, st, tid);
        load_tile_async<BM, THREADS>(Alo, bm, kb, st + SA, tid);
        load_tile_async<BN, THREADS>(Bhi, (size_t)bn, kb, st + 2 * SA, tid);
        load_tile_async<BN, THREADS>(Blo, (size_t)bn, kb, st + 2 * SA + SB, tid);
        CP_COMMIT();
    };

    issue_loads(0, 0);

    for (int c = 0; c < NCHUNK; ++c) {
        if (c + 1 < NCHUNK) {
            issue_loads(c + 1, (c + 1) & 1);
            CP_WAIT(1);
        } else {
            CP_WAIT(0);
        }
        __syncthreads();

        const uint32_t st = sbase + (uint32_t)((c & 1) * STAGE);
        const uint32_t aHi = st + (uint32_t)((wm + arow) * 128);
        const uint32_t aLo = aHi + SA;
        const uint32_t bHi = st + 2 * SA + (uint32_t)((wn + brow) * 128);
        const uint32_t bLo = bHi + SB;

#pragma unroll
        for (int kk = 0; kk < 4; ++kk) {
            const uint32_t ka = (uint32_t)(kk * 32 + akb) ^ swx;
            const uint32_t kb2 = (uint32_t)(kk * 32 + bkb) ^ swx;
            uint32_t ah[WM / 16][4], al[WM / 16][4], bh[WN / 16][4], bl[WN / 16][4];
#pragma unroll
            for (int mi = 0; mi < WM / 16; ++mi) {
                ldsm4(ah[mi], aHi + mi * 2048 + ka);
                ldsm4(al[mi], aLo + mi * 2048 + ka);
            }
#pragma unroll
            for (int nj = 0; nj < WN / 16; ++nj) {
                ldsm4(bh[nj], bHi + nj * 2048 + kb2);
                ldsm4(bl[nj], bLo + nj * 2048 + kb2);
            }
#pragma unroll
            for (int mi = 0; mi < WM / 16; ++mi)
#pragma unroll
                for (int ni = 0; ni < WN / 8; ++ni)
                    mma16816(acc[mi][ni], ah[mi],
                             bh[ni >> 1][2 * (ni & 1)], bh[ni >> 1][2 * (ni & 1) + 1]);
#pragma unroll
            for (int mi = 0; mi < WM / 16; ++mi)
#pragma unroll
                for (int ni = 0; ni < WN / 8; ++ni)
                    mma16816(acc[mi][ni], ah[mi],
                             bl[ni >> 1][2 * (ni & 1)], bl[ni >> 1][2 * (ni & 1) + 1]);
#pragma unroll
            for (int mi = 0; mi < WM / 16; ++mi)
#pragma unroll
                for (int ni = 0; ni < WN / 8; ++ni)
                    mma16816(acc[mi][ni], al[mi],
                             bh[ni >> 1][2 * (ni & 1)], bh[ni >> 1][2 * (ni & 1) + 1]);
        }
        __syncthreads();
    }

    const int g = lane >> 2, tg = lane & 3;
#pragma unroll
    for (int mi = 0; mi < WM / 16; ++mi) {
#pragma unroll
        for (int ni = 0; ni < WN / 8; ++ni) {
            const size_t r0 = bm + (size_t)(wm + mi * 16 + g);
            const size_t r1 = r0 + 8;
            const int c0 = bn + wn + ni * 8 + 2 * tg;
            float b0 = bih[c0] + bhh[c0];
            float b1 = bih[c0 + 1] + bhh[c0 + 1];
            *(float2*)(out_f + r0 * HH + c0) =
                make_float2(acc[mi][ni][0] + b0, acc[mi][ni][1] + b1);
            *(float2*)(out_f + r1 * HH + c0) =
                make_float2(acc[mi][ni][2] + b0, acc[mi][ni][3] + b1);
        }
    }
}

// -------------------- persistent recurrence kernel -------------------------
// 128 CTAs (one/SM), 256 threads. CTA tile 32(M)x64(N). W_hh resident in smem.
// Producer flags + acquire polls; self A-chunk kept in smem (computed first).
#define NCTA 128
#define PBM 32
#define PBN 64
// smem map
#define SMB 0                       // W_hh: hi [0,64K), lo [64K,128K); chunk stride 8K
#define SMB_SPLIT 65536
#define SMB_CHUNK 8192
#define SMA 131072                  // A (h): 8 chunks x 8K (hi +0, lo +4096)
#define SMA_CHUNK 8192
#define SMXP 196608                 // xp tile: 32x64 f32 = 8K
#define SMMISC 204800               // flag base broadcast
#define PSMEM 204928

__global__ void __launch_bounds__(256, 1)
rnn_persistent_kernel(const float* __restrict__ xp,
                      const __nv_bfloat16* __restrict__ whh_h,
                      const __nv_bfloat16* __restrict__ whh_l,
                      __nv_bfloat16* __restrict__ hhi, __nv_bfloat16* __restrict__ hlo,
                      float* __restrict__ out)
{
    extern __shared__ char smem[];
    const uint32_t sb = smem_u32(smem);
    const int tid = threadIdx.x;
    const int wid = tid >> 5, lane = tid & 31;
    const int mtile = blockIdx.x >> 3;      // 0..15
    const int ntile = blockIdx.x & 7;       // 0..7
    const size_t bm = (size_t)mtile * PBM;
    const int bn = ntile * PBN;
    const int wm = (wid & 1) * 16;          // 2x4 warp grid: WM=16, WN=16
    const int wn = (wid >> 1) * 16;

    // flag base: read OWN flag (cannot have advanced before my launch)
    if (tid == 0) {
        unsigned fb0;
        asm volatile("ld.volatile.global.u32 %0, [%1];"
                     : "=r"(fb0) : "l"(&g_flag[mtile][ntile * 32]));
        *(unsigned*)(smem + SMMISC) = fb0;
    }

    // ---- load resident W_hh tiles (rows bn..bn+64, all K), both splits ----
#pragma unroll
    for (int i = 0; i < 32; ++i) {
        int v = i * 256 + tid;              // 8192 granules
        int split = v >> 12;
        int rem = v & 4095;
        int chunk = rem >> 9;
        int rr = rem & 511;
        int row = rr >> 3, g16 = rr & 7;
        const __nv_bfloat16* src = (split ? whh_l : whh_h);
        uint32_t dst = sb + SMB + split * SMB_SPLIT + chunk * SMB_CHUNK
                     + row * 128 + (uint32_t)((g16 * 16) ^ ((row & 7) * 16));
        cp16(dst, src + (size_t)(bn + row) * HH + chunk * 64 + g16 * 8);
    }
    CP_COMMIT();

    // self-chunk smem store helper (4B pair at (row, even col), swizzled)
    auto sts4 = [&](uint32_t base, int row, int lc, uint32_t val) {
        uint32_t bc = (uint32_t)(lc * 2);
        uint32_t off = (uint32_t)(row * 128)
                     + ((bc & ~15u) ^ (((uint32_t)(row & 7)) << 4)) + (bc & 15u);
        *(uint32_t*)(smem + base + off) = val;
    };
    const uint32_t selfA = (uint32_t)(SMA + ntile * SMA_CHUNK);

    // ---- step 0: h1 = tanh(xp_0) for this tile (overlaps W load) ----------
#pragma unroll
    for (int i = 0; i < 2; ++i) {
        int v = i * 256 + tid;              // 512 float4 granules
        int row = v >> 4, c4 = v & 15;
        const float4 x = *(const float4*)(xp + (bm + row) * HH + bn + c4 * 4);
        float v0 = fast_tanh(x.x), v1 = fast_tanh(x.y);
        float v2 = fast_tanh(x.z), v3 = fast_tanh(x.w);
        __nv_bfloat16 h0, l0, h1, l1, h2, l2, h3, l3;
        split1(v0, h0, l0); split1(v1, h1, l1);
        split1(v2, h2, l2); split1(v3, h3, l3);
        __nv_bfloat162 hp0(h0, h1), hp1(h2, h3), lp0(l0, l1), lp1(l2, l3);
        size_t off = (bm + row) * HH + bn + c4 * 4;
        *(uint2*)(hhi + off) = make_uint2(*(uint32_t*)&hp0, *(uint32_t*)&hp1);
        *(uint2*)(hlo + off) = make_uint2(*(uint32_t*)&lp0, *(uint32_t*)&lp1);
        sts4(selfA, row, c4 * 4, *(uint32_t*)&hp0);
        sts4(selfA, row, c4 * 4 + 2, *(uint32_t*)&hp1);
        sts4(selfA + 4096, row, c4 * 4, *(uint32_t*)&lp0);
        sts4(selfA + 4096, row, c4 * 4 + 2, *(uint32_t*)&lp1);
    }
    CP_WAIT(0);
    __syncthreads();
    const unsigned fb = *(const unsigned*)(smem + SMMISC);
    if (tid == 0)
        asm volatile("red.release.gpu.global.add.u32 [%0], %1;"
                     :: "l"(&g_flag[mtile][ntile * 32]), "r"(1u) : "memory");

    // ldmatrix lane geometry
    const int sub = lane >> 3, li = lane & 7;
    const int arow = (sub & 1) * 8 + li;
    const int akb  = (sub >> 1) * 16;
    const int brow = (sub >> 1) * 8 + li;
    const int bkb  = (sub & 1) * 16;
    const uint32_t swx = (uint32_t)(li * 16);
    const int g = lane >> 2, tg = lane & 3;

    for (int t = 1; t < TT; ++t) {
        const __nv_bfloat16* Ah = hhi;
        const __nv_bfloat16* Al = hlo;
        const float* xpt = xp + (size_t)t * BH;

        float acc[2][4];
#pragma unroll
        for (int ni = 0; ni < 2; ++ni)
#pragma unroll
            for (int q = 0; q < 4; ++q) acc[ni][q] = 0.0f;

        auto compute_chunk = [&](int c) {
            const uint32_t aHi = sb + SMA + c * SMA_CHUNK + (uint32_t)((wm + arow) * 128);
            const uint32_t aLo = aHi + 4096;
            const uint32_t bHi = sb + SMB + c * SMB_CHUNK + (uint32_t)((wn + brow) * 128);
            const uint32_t bLo = bHi + SMB_SPLIT;
#pragma unroll
            for (int kk = 0; kk < 4; ++kk) {
                const uint32_t ka  = (uint32_t)(kk * 32 + akb) ^ swx;
                const uint32_t kb2 = (uint32_t)(kk * 32 + bkb) ^ swx;
                uint32_t ah[4], al4[4], bh[4], bl[4];
                ldsm4(ah, aHi + ka);
                ldsm4(al4, aLo + ka);
                ldsm4(bh, bHi + kb2);
                ldsm4(bl, bLo + kb2);
#pragma unroll
                for (int ni = 0; ni < 2; ++ni)
                    mma16816(acc[ni], ah, bh[2 * ni], bh[2 * ni + 1]);
#pragma unroll
                for (int ni = 0; ni < 2; ++ni)
                    mma16816(acc[ni], ah, bl[2 * ni], bl[2 * ni + 1]);
#pragma unroll
                for (int ni = 0; ni < 2; ++ni)
                    mma16816(acc[ni], al4, bh[2 * ni], bh[2 * ni + 1]);
            }
        };

        // phase 0: self chunk (A already in smem; epilogue writes ordered by
        // the syncthreads at the end of the previous iteration / step 0)
        compute_chunk(ntile);

        // phase 1: wait for the 7 peer producers of h_t
        if (tid < 7) {
            const int c = (ntile + 1 + tid) & 7;
            const unsigned* fl = &g_flag[mtile][c * 32];
            const unsigned target = fb + (unsigned)t;
            unsigned v;
            do {
                asm volatile("ld.acquire.gpu.global.u32 %0, [%1];" : "=r"(v) : "l"(fl));
            } while ((int)(v - target) < 0);
        }
        __syncthreads();

        // phase 2: issue loads — xp first (group 1), then 7 chunks (groups 2..8)
        {
#pragma unroll
            for (int i = 0; i < 2; ++i) {
                int v = i * 256 + tid;       // 512 granules (32x64 f32)
                int row = v >> 4, g16 = v & 15;
                cp16(sb + SMXP + row * 256 + g16 * 16,
                     xpt + (bm + row) * HH + bn + g16 * 4);
            }
            CP_COMMIT();
        }
#pragma unroll
        for (int j = 1; j < 8; ++j) {
            const int c = (ntile + j) & 7;
            const uint32_t base = sb + SMA + c * SMA_CHUNK;
#pragma unroll
            for (int i = 0; i < 2; ++i) {
                int v = i * 256 + tid;       // 512 granules (hi 256 + lo 256)
                int split = v >> 8;
                int rr = v & 255;
                int row = rr >> 3, g16 = rr & 7;
                const __nv_bfloat16* src = (split ? Al : Ah);
                uint32_t dst = base + split * 4096 + row * 128
                             + (uint32_t)((g16 * 16) ^ ((row & 7) * 16));
                cp16(dst, src + (bm + (size_t)row) * HH + c * 64 + g16 * 8);
            }
            CP_COMMIT();
        }

        // phase 3: compute remote chunks with staged waits
#pragma unroll
        for (int j = 1; j < 8; j += 2) {
            if (j == 1)      { CP_WAIT(5); }
            else if (j == 3) { CP_WAIT(3); }
            else if (j == 5) { CP_WAIT(1); }
            else             { CP_WAIT(0); }
            __syncthreads();
            compute_chunk((ntile + j) & 7);
            if (j + 1 < 8) compute_chunk((ntile + j + 1) & 7);
        }

        // phase 4: epilogue — tanh(acc + xp); write self smem chunk + global
        const float* sXP = (const float*)(smem + SMXP);
#pragma unroll
        for (int ni = 0; ni < 2; ++ni) {
            const int lr0 = wm + g;
            const int lc  = wn + ni * 8 + 2 * tg;
            const size_t r0 = bm + (size_t)lr0;
            const size_t r1 = r0 + 8;
            const int c0 = bn + lc;
            float2 x0 = *(const float2*)(sXP + lr0 * PBN + lc);
            float2 x1 = *(const float2*)(sXP + (lr0 + 8) * PBN + lc);
            float v0 = fast_tanh(acc[ni][0] + x0.x);
            float v1 = fast_tanh(acc[ni][1] + x0.y);
            float v2 = fast_tanh(acc[ni][2] + x1.x);
            float v3 = fast_tanh(acc[ni][3] + x1.y);
            if (t == TT - 1) {
                *(float2*)(out + r0 * HH + c0) = make_float2(v0, v1);
                *(float2*)(out + r1 * HH + c0) = make_float2(v2, v3);
            } else {
                __nv_bfloat16 h0, l0, h1, l1, h2, l2, h3, l3;
                split1(v0, h0, l0); split1(v1, h1, l1);
                split1(v2, h2, l2); split1(v3, h3, l3);
                __nv_bfloat162 hp0(h0, h1), hp1(h2, h3), lp0(l0, l1), lp1(l2, l3);
                *(uint32_t*)(hhi + r0 * HH + c0) = *(uint32_t*)&hp0;
                *(uint32_t*)(hlo + r0 * HH + c0) = *(uint32_t*)&lp0;
                *(uint32_t*)(hhi + r1 * HH + c0) = *(uint32_t*)&hp1;
                *(uint32_t*)(hlo + r1 * HH + c0) = *(uint32_t*)&lp1;
                sts4(selfA, lr0, lc, *(uint32_t*)&hp0);
                sts4(selfA + 4096, lr0, lc, *(uint32_t*)&lp0);
                sts4(selfA, lr0 + 8, lc, *(uint32_t*)&hp1);
                sts4(selfA + 4096, lr0 + 8, lc, *(uint32_t*)&lp1);
            }
        }

        __syncthreads();   // orders: epilogue STG/STS of all threads, next phase0
        if (tid == 0 && t < TT - 1)
            asm volatile("red.release.gpu.global.add.u32 [%0], %1;"
                         :: "l"(&g_flag[mtile][ntile * 32]), "r"(1u) : "memory");
    }
}

// -------------------- launcher ---------------------------------------------
extern "C" void kernel_launch(void* const* d_in, const int* in_sizes, int n_in,
                              void* d_out, int out_size)
{
    const float* X   = (const float*)d_in[0];
    const float* Wih = (const float*)d_in[1];
    const float* Whh = (const float*)d_in[2];
    const float* bih = (const float*)d_in[3];
    const float* bhh = (const float*)d_in[4];
    float* out = (float*)d_out;

    float* xp;
    __nv_bfloat16 *xhi, *xlo, *wih_h, *wih_l, *whh_h, *whh_l, *hhi, *hlo;
    cudaGetSymbolAddress((void**)&xp, g_xp);
    cudaGetSymbolAddress((void**)&xhi, g_xhi);
    cudaGetSymbolAddress((void**)&xlo, g_xlo);
    cudaGetSymbolAddress((void**)&wih_h, g_wih_h);
    cudaGetSymbolAddress((void**)&wih_l, g_wih_l);
    cudaGetSymbolAddress((void**)&whh_h, g_whh_h);
    cudaGetSymbolAddress((void**)&whh_l, g_whh_l);
    cudaGetSymbolAddress((void**)&hhi, g_hhi);
    cudaGetSymbolAddress((void**)&hlo, g_hlo);

    constexpr int SMEM_XP = 2 * (2 * 128 * 128 + 2 * 128 * 128);  // 131072
    cudaFuncSetAttribute(gemm_split_kernel<128, 128, 64, 32, false>,
                         cudaFuncAttributeMaxDynamicSharedMemorySize, SMEM_XP);
    cudaFuncSetAttribute(rnn_persistent_kernel,
                         cudaFuncAttributeMaxDynamicSharedMemorySize, PSMEM);

    // 1) hi/lo splits
    split_kernel<<<128, 256>>>(Wih, wih_h, wih_l, HH * DD / 4);
    split_kernel<<<128, 256>>>(Whh, whh_h, whh_l, HH * HH / 4);
    split_kernel<<<8192, 256>>>(X, xhi, xlo, (int)((size_t)TT * BB * DD / 4));

    // 2) xp = X @ Wih^T + (b_ih + b_hh) for all timesteps
    {
        dim3 g(HH / 128, (TT * BB) / 128);
        gemm_split_kernel<128, 128, 64, 32, false><<<g, 256, SMEM_XP>>>(
            xhi, xlo, wih_h, wih_l, nullptr, bih, bhh, xp, nullptr, nullptr);
    }

    // 3) entire recurrence in one persistent kernel (producer flags)
    rnn_persistent_kernel<<<NCTA, 256, PSMEM>>>(xp, whh_h, whh_l, hhi, hlo, out);
}